// round 17
// baseline (speedup 1.0000x reference)
#include <cuda_runtime.h>
#include <cstdint>

// Problem constants
#define BB 512
#define VV 32768
#define CC 16
#define TT 256          // threads per block: 8 warps = 4 quads x 2 halves
#define VT 32           // v per CTA (lane = v)

// EMA coefficient: 1 - MOMENTUM = 2/(STEPS_PER_EPOCH+1)
#define ALPHA ((float)(2.0 / 1001.0))

// ---------------------------------------------------------------------------
// Fused kernel: sorted class segments + quad-specialized scalar gather,
// tuned to 8 CTAs/SM (regs<=32, single wave of 1024 CTAs).
// Warp (q = warp&3, h = warp>>2), lane = v. Warp processes sorted samples of
// classes [4q,4q+4), half h. Channel index constant per segment -> no
// per-iteration selection ALU. Batch-2 keeps only 4 live addresses.
// ---------------------------------------------------------------------------
__global__ void __launch_bounds__(TT, 8)
fused_centroid_kernel(const float* __restrict__ sparse,
                      const float* __restrict__ W,
                      const int* __restrict__ labels,
                      const float* __restrict__ centroids,
                      const int* __restrict__ initialized,
                      float* __restrict__ out)
{
    __shared__ int   s_lab[BB];            // raw labels (staging for sort)
    __shared__ int   s_ord[BB];            // class-sorted sample indices
    __shared__ int   s_cnt[CC];            // global class counts
    __shared__ int   s_off[CC];            // class segment offsets
    __shared__ float s_red[2 * CC * VT];   // [h][c][v] partials (4 KB)

    const int tid = threadIdx.x;

    // Stage labels in smem (all threads help).
    #pragma unroll
    for (int i = tid; i < BB; i += TT)
        s_lab[i] = labels[i];
    __syncthreads();

    // Deterministic ballot counting sort (warp 0), labels re-read from smem
    // each round so no 16-deep register array survives into the main loop.
    if (tid < 32) {
        const int lane = tid;
        const unsigned lt = (1u << lane) - 1u;
        int base = 0;
        for (int c = 0; c < CC; ++c) {
            if (lane == 0) s_off[c] = base;
            int cbase = base;
            for (int k = 0; k < BB / 32; ++k) {
                const int l = s_lab[k * 32 + lane];
                const unsigned m = __ballot_sync(0xffffffffu, l == c);
                if (l == c)
                    s_ord[cbase + __popc(m & lt)] = k * 32 + lane;
                cbase += __popc(m);
            }
            if (lane == 0) s_cnt[c] = cbase - base;
            base = cbase;
        }
    }
    __syncthreads();

    const int warp = tid >> 5;
    const int lane = tid & 31;
    const int q    = warp & 3;      // class quad: classes 4q..4q+3
    const int h    = warp >> 2;     // sample half within each segment
    const int v    = blockIdx.x * VT + lane;

    const float* __restrict__ sp = sparse + v;            // + (b<<15)
    const float* __restrict__ Wv = W + (size_t)v * CC;    // + (b<<19) + c

    #pragma unroll
    for (int r = 0; r < 4; ++r) {
        const int c  = 4 * q + r;
        const int n  = s_cnt[c];
        const int n0 = (n + 1) >> 1;                      // h=0 share
        const int js = s_off[c] + (h ? n0 : 0);
        const int je = s_off[c] + (h ? n : n0);
        const float* __restrict__ Wc = Wv + c;

        float acc = 0.0f;
        int j = js;
        // batch-2: 4 independent LDGs in flight, 4 live address pairs
        for (; j + 2 <= je; j += 2) {
            const int b0 = s_ord[j], b1 = s_ord[j + 1];
            const float w0 = __ldcs(Wc + ((size_t)b0 << 19));
            const float w1 = __ldcs(Wc + ((size_t)b1 << 19));
            const float x0 = __ldcs(sp + ((size_t)b0 << 15));
            const float x1 = __ldcs(sp + ((size_t)b1 << 15));
            acc += fabsf(w0 * x0);
            acc += fabsf(w1 * x1);
        }
        if (j < je) {
            const int b = s_ord[j];
            acc += fabsf(__ldcs(Wc + ((size_t)b << 19)) *
                         __ldcs(sp + ((size_t)b << 15)));
        }

        s_red[(h * CC + c) * VT + lane] = acc;
    }
    __syncthreads();

    // 512 (c, v) outputs per CTA; 256 threads -> 2 each.
    #pragma unroll
    for (int p = tid; p < CC * VT; p += TT) {
        const int c  = p >> 5;
        const int pv = p & 31;
        const float sum = s_red[(0 * CC + c) * VT + pv] +
                          s_red[(1 * CC + c) * VT + pv];

        const int n  = s_cnt[c];
        const int vo = blockIdx.x * VT + pv;
        const float cen = centroids[(size_t)c * VV + vo];
        float o;
        if (n > 0) {
            const float mean = sum / (float)n;
            o = (initialized[c] != 0) ? (cen + ALPHA * (mean - cen)) : mean;
        } else {
            o = cen;
        }
        out[(size_t)c * VV + vo] = o;
    }
}

// ---------------------------------------------------------------------------
// Launch: graph-capturable, allocation-free. ONE kernel.
// Inputs identified BY ELEMENT COUNT (robust to metadata ordering):
//   W_eff       f32[B,V,C] -> 268435456 elems
//   sparse_vec  f32[B,V]   ->  16777216 elems
//   centroids   f32[C,V]   ->    524288 elems
//   labels      i32[B]     ->       512 elems
//   initialized i32[C]     ->        16 elems (bool widened to int32)
// Output: f32[C,V].
// ---------------------------------------------------------------------------
extern "C" void kernel_launch(void* const* d_in, const int* in_sizes, int n_in,
                              void* d_out, int out_size)
{
    const float* sparse    = nullptr;
    const float* W         = nullptr;
    const int*   labels    = nullptr;
    const float* centroids = nullptr;
    const int*   init      = nullptr;
    float*       out       = (float*)d_out;

    for (int i = 0; i < n_in; ++i) {
        switch (in_sizes[i]) {
            case BB * VV:            sparse    = (const float*)d_in[i]; break; // 16777216
            case BB:                 labels    = (const int*)d_in[i];   break; // 512
            case CC * VV:            centroids = (const float*)d_in[i]; break; // 524288
            case CC:                 init      = (const int*)d_in[i];   break; // 16
            default:                 W         = (const float*)d_in[i]; break; // 268435456
        }
    }

    fused_centroid_kernel<<<VV / VT, TT>>>(sparse, W, labels, centroids, init, out);
}